// round 12
// baseline (speedup 1.0000x reference)
#include <cuda_runtime.h>
#include <cuda_fp16.h>
#include <cstdint>

#define MAXN 100000
#define BINSZ 32
#define NBINS ((MAXN + BINSZ - 1) / BINSZ)    // 3125
#define CAPB  1280                            // Poisson(1024) + 8 sigma
#define SSTRIDE 36                            // floats/node row in smem (16B-aligned, bank-skewed)

// ---- device scratch (no allocations allowed) ----
__device__ float g_deg [MAXN];
__device__ float g_dinv[MAXN];
__device__ int   g_bcnt[NBINS];
__device__ uint2 g_rec[(size_t)NBINS * CAPB];          // 32MB edge records
__device__ __align__(128) float4 g_xp   [MAXN];        // xs = dinv*x (w=0)
__device__ __align__(128) float4 g_aggx [MAXN];        // layer-0 agg of xs
__device__ __align__(128) float4 g_av   [MAXN];        // (a0,a1,a2,dinv)
__device__ __align__(128) float4 g_agg1f[MAXN * 8];    // final per-node features fp32

__device__ __forceinline__ void red_add_v4f(float4* addr, float4 v) {
    atomicAdd(addr, v);
}

// K1: deg=1 (self-loop), bin counters = 0
__global__ void k_init(int n) {
    int i = blockIdx.x * blockDim.x + threadIdx.x;
    if (i < n) g_deg[i] = 1.0f;
    if (i < NBINS) g_bcnt[i] = 0;
}

// K2: merged deg-scatter + record binning (one edge-stream pass)
__global__ void k_degbin(const int* __restrict__ idx, const float* __restrict__ w, int E) {
    int e = blockIdx.x * blockDim.x + threadIdx.x;
    if (e >= E) return;
    int row = idx[e];
    int col = idx[E + e];
    float ww = w[e];
    atomicAdd(&g_deg[col], ww);
    int bin = col >> 5, colOff = col & 31;
    int p = atomicAdd(&g_bcnt[bin], 1);
    if (p < CAPB) {
        unsigned short hb = __half_as_ushort(__float2half_rn(ww));
        g_rec[(size_t)bin * CAPB + p] = make_uint2((unsigned)row,
                                                  ((unsigned)colOff << 16) | (unsigned)hb);
    }
}

// K3: dinv = rsqrt(deg); xs = dinv*x; seed layer-0 agg with self term
__global__ void k_dinv(const float* __restrict__ x, int n) {
    int i = blockIdx.x * blockDim.x + threadIdx.x;
    if (i >= n) return;
    float d  = g_deg[i];
    float dv = d > 0.f ? rsqrtf(d) : 0.f;
    g_dinv[i] = dv;
    float4 xs = make_float4(x[3*i] * dv, x[3*i+1] * dv, x[3*i+2] * dv, 0.f);
    g_xp[i]   = xs;
    g_aggx[i] = xs;
}

// K4: layer-0 edge pass (factorized norm), fp32 red.v4
__global__ void k_edge0(const int* __restrict__ idx, const float* __restrict__ w, int E) {
    int e = blockIdx.x * blockDim.x + threadIdx.x;
    if (e >= E) return;
    int row = idx[e];
    int col = idx[E + e];
    float ww = w[e];
    float4 v = g_xp[row];
    red_add_v4f(&g_aggx[col], make_float4(v.x * ww, v.y * ww, v.z * ww, 0.f));
}

// K5: av = (dinv*agg0, dinv) per node
__global__ void k_node0(int n) {
    int i = blockIdx.x * blockDim.x + threadIdx.x;
    if (i >= n) return;
    float4 ag = g_aggx[i];
    float dv  = g_dinv[i];
    g_av[i] = make_float4(ag.x * dv, ag.y * dv, ag.z * dv, dv);
}

// K6: phase-2 — block per bin; 8 warps with private fp32 smem copies.
// Quad of 4 lanes per record; lane j owns features [8j,8j+8). Collisions on
// colOff among quads serialized via match rounds. Writeout fuses self term
// and final dinv scale.
__global__ __launch_bounds__(256) void k_binagg(const float* __restrict__ W0,
                                                const float* __restrict__ b0, int n) {
    int bin = blockIdx.x;
    __shared__ __align__(16) float sacc[8][BINSZ * SSTRIDE];
    int tid  = threadIdx.x;
    int lane = tid & 31, wrp = tid >> 5;
    int quad = lane >> 2, j = lane & 3;
    for (int i = tid; i < 8 * BINSZ * SSTRIDE; i += 256) ((float*)sacc)[i] = 0.f;
    float w0r[8], w1r[8], w2r[8], b0r[8];
#pragma unroll
    for (int k = 0; k < 8; k++) {
        int c = 8 * j + k;
        w0r[k] = W0[c]; w1r[k] = W0[32 + c]; w2r[k] = W0[64 + c]; b0r[k] = b0[c];
    }
    __syncthreads();
    int cnt = min(g_bcnt[bin], CAPB);
    const uint2* recs = g_rec + (size_t)bin * CAPB;
    for (int base = wrp * 8; base < cnt; base += 64) {
        int i = base + quad;
        bool valid = i < cnt;
        int colOff = 0;
        float f[8];
        if (valid) {
            uint2 rc = recs[i];
            colOff = (int)(rc.y >> 16);
            float ww = __half2float(__ushort_as_half((unsigned short)(rc.y & 0xffffu)));
            float4 av = __ldg(g_av + rc.x);
            float s = av.w * ww;
#pragma unroll
            for (int k = 0; k < 8; k++) {
                float h = fmaf(av.x, w0r[k], fmaf(av.y, w1r[k], fmaf(av.z, w2r[k], b0r[k])));
                f[k] = fmaxf(h, 0.f) * s;
            }
        }
        unsigned key = valid ? (unsigned)colOff : 64u + (unsigned)quad;
        unsigned m = __match_any_sync(0xffffffffu, key);
        int pre = __popc(m & ((1u << (quad * 4)) - 1)) >> 2;
        int rounds = (int)__reduce_max_sync(0xffffffffu, (unsigned)pre) + 1;
        for (int r = 0; r < rounds; r++) {
            if (valid && pre == r) {
                float* dst = &sacc[wrp][colOff * SSTRIDE + j * 8];
                float4 x0 = *(float4*)dst;
                float4 x1 = *(float4*)(dst + 4);
                x0.x += f[0]; x0.y += f[1]; x0.z += f[2]; x0.w += f[3];
                x1.x += f[4]; x1.y += f[5]; x1.z += f[6]; x1.w += f[7];
                *(float4*)dst = x0;
                *(float4*)(dst + 4) = x1;
            }
            __syncwarp();
        }
    }
    __syncthreads();
    // writeout: node = tid>>3 (32 nodes), fq = tid&7 (feature quad)
    int node = tid >> 3, fq = tid & 7;
    int gid = bin * BINSZ + node;
    if (gid < n) {
        float s0 = 0.f, s1 = 0.f, s2 = 0.f, s3 = 0.f;
#pragma unroll
        for (int wcp = 0; wcp < 8; wcp++) {
            const float* src = &sacc[wcp][node * SSTRIDE + fq * 4];
            s0 += src[0]; s1 += src[1]; s2 += src[2]; s3 += src[3];
        }
        float4 av = g_av[gid];
        float dv = av.w;
        float o[4]; float sv[4] = {s0, s1, s2, s3};
#pragma unroll
        for (int k = 0; k < 4; k++) {
            int c = fq * 4 + k;
            float h = fmaf(av.x, __ldg(W0 + c),
                      fmaf(av.y, __ldg(W0 + 32 + c),
                      fmaf(av.z, __ldg(W0 + 64 + c), __ldg(b0 + c))));
            float self = fmaxf(h, 0.f) * dv;      // hs1 (includes dinv)
            o[k] = (sv[k] + self) * dv;           // final dinv scale
        }
        g_agg1f[gid * 8 + fq] = make_float4(o[0], o[1], o[2], o[3]);
    }
}

// K7: per-graph block: h2 = relu(agg1 @ W1 + b1), mean-pool over sorted-batch
// range (binary search), head dot with Wr. (dinv already applied.)
__global__ void k_pool(const int* __restrict__ batch,
                       const float* __restrict__ W1, const float* __restrict__ b1,
                       const float* __restrict__ Wr, const float* __restrict__ br,
                       float* __restrict__ out, int n) {
    int g = blockIdx.x;
    __shared__ float sW1[32 * 32];
    __shared__ float sb1[32];
    __shared__ float sWr[32];
    __shared__ int   sse[2];
    __shared__ float stile[8][33];
    __shared__ float spool[8][32];
    int tid = threadIdx.x;  // 256 threads
    for (int k = tid; k < 1024; k += 256) sW1[k] = W1[k];
    if (tid < 32) { sb1[tid] = b1[tid]; sWr[tid] = Wr[tid]; }
    if (tid < 2) {
        int key = g + tid;
        int lo = 0, hi = n;
        while (lo < hi) { int mid = (lo + hi) >> 1; if (batch[mid] < key) lo = mid + 1; else hi = mid; }
        sse[tid] = lo;
    }
    __syncthreads();
    int start = sse[0], end = sse[1];
    int feat = tid & 31, slot = tid >> 5;
    const float* agg = (const float*)g_agg1f;
    float acc = 0.f;
    for (int base = start; base < end; base += 8) {
        int nload = min(8, end - base);
        __syncthreads();
        if (slot < nload) {
            int node = base + slot;
            stile[slot][feat] = agg[node * 32 + feat];
        }
        __syncthreads();
        if (slot < nload) {
            float v = sb1[feat];
#pragma unroll
            for (int jj = 0; jj < 32; jj++) v = fmaf(stile[slot][jj], sW1[jj * 32 + feat], v);
            acc += fmaxf(v, 0.f);
        }
    }
    spool[slot][feat] = acc;
    __syncthreads();
    if (tid < 32) {
        float s = 0.f;
#pragma unroll
        for (int k = 0; k < 8; k++) s += spool[k][tid];
        float cnt = (float)(end - start);
        float hg = s / fmaxf(cnt, 1.f);
        float p = hg * sWr[tid];
#pragma unroll
        for (int off = 16; off; off >>= 1) p += __shfl_down_sync(0xffffffffu, p, off);
        if (tid == 0) out[g] = p + br[0];
    }
}

extern "C" void kernel_launch(void* const* d_in, const int* in_sizes, int n_in,
                              void* d_out, int out_size) {
    const float* x     = (const float*)d_in[0];
    const int*   ei    = (const int*)d_in[1];
    const float* ew    = (const float*)d_in[2];
    const int*   batch = (const int*)d_in[3];
    const float* W0    = (const float*)d_in[4];
    const float* b0    = (const float*)d_in[5];
    const float* W1    = (const float*)d_in[6];
    const float* b1    = (const float*)d_in[7];
    const float* Wr    = (const float*)d_in[8];
    const float* br    = (const float*)d_in[9];
    float* out = (float*)d_out;

    int n = in_sizes[0] / 3;
    int E = in_sizes[2];
    int G = out_size;
    const int TB = 256;
    int initN = (n > NBINS ? n : NBINS);

    k_init  <<<(initN + TB - 1) / TB, TB>>>(n);
    k_degbin<<<(E + TB - 1) / TB, TB>>>(ei, ew, E);
    k_dinv  <<<(n + TB - 1) / TB, TB>>>(x, n);
    k_edge0 <<<(E + TB - 1) / TB, TB>>>(ei, ew, E);
    k_node0 <<<(n + TB - 1) / TB, TB>>>(n);
    k_binagg<<<NBINS, 256>>>(W0, b0, n);
    k_pool  <<<G, 256>>>(batch, W1, b1, Wr, br, out, n);
}

// round 14
// speedup vs baseline: 1.8889x; 1.8889x over previous
#include <cuda_runtime.h>
#include <cuda_fp16.h>
#include <cstdint>

#define MAXN 100000

// ---- device scratch (no allocations allowed) ----
__device__ float g_deg [MAXN];
__device__ float g_dinv[MAXN];
__device__ __align__(128) float4 g_xp  [MAXN];      // xs = dinv*x, padded (w=0)
__device__ __align__(128) float4 g_aggx[MAXN];      // layer-0 agg of xs (fp32)
__device__ __align__(128) float4 g_av  [MAXN];      // (a0,a1,a2,dinv): rank-3 h1 code
__device__ __align__(128) uint2  g_aggh[MAXN * 8];  // layer-1 agg fp16 [N x 32]

__device__ __forceinline__ void red_add_v4f(float4* addr, float4 v) {
    atomicAdd(addr, v);   // native fp32 vector red (cc >= 9.0)
}
__device__ __forceinline__ void red_add_v4h(void* addr, unsigned int a, unsigned int b,
                                            unsigned int c, unsigned int d) {
    asm volatile("red.global.add.noftz.v4.f16x2 [%0], {%1,%2,%3,%4};"
                 :: "l"(__cvta_generic_to_global(addr)),
                    "r"(a), "r"(b), "r"(c), "r"(d) : "memory");
}

// K1: deg starts at 1.0 (self-loop weight)
__global__ void k_init(int n) {
    int i = blockIdx.x * blockDim.x + threadIdx.x;
    if (i < n) g_deg[i] = 1.0f;
}

// K2: deg[col] += w over all edges
__global__ void k_deg(const int* __restrict__ idx, const float* __restrict__ w, int E) {
    int e = blockIdx.x * blockDim.x + threadIdx.x;
    if (e >= E) return;
    atomicAdd(&g_deg[idx[E + e]], w[e]);
}

// K3: dinv = rsqrt(deg); xs = dinv*x; seed layer-0 agg with self term xs
__global__ void k_dinv(const float* __restrict__ x, int n) {
    int i = blockIdx.x * blockDim.x + threadIdx.x;
    if (i >= n) return;
    float d  = g_deg[i];
    float dv = d > 0.f ? rsqrtf(d) : 0.f;
    g_dinv[i] = dv;
    float4 xs = make_float4(x[3*i] * dv, x[3*i+1] * dv, x[3*i+2] * dv, 0.f);
    g_xp[i]   = xs;
    g_aggx[i] = xs;
}

// K4: layer-0 edge pass (factorized norm), fp32 red.v4
__global__ void k_edge0(const int* __restrict__ idx, const float* __restrict__ w, int E) {
    int e = blockIdx.x * blockDim.x + threadIdx.x;
    if (e >= E) return;
    int row = idx[e];
    int col = idx[E + e];
    float ww = w[e];
    float4 v = g_xp[row];
    red_add_v4f(&g_aggx[col], make_float4(v.x * ww, v.y * ww, v.z * ww, 0.f));
}

// K5: per node: a = dinv*agg0; store (a,dinv); seed layer-1 agg with self
// h1 = dinv*relu(a@W0 + b0) in fp16. Thread per node (light compute).
__global__ void k_node0(const float* __restrict__ W0, const float* __restrict__ b0, int n) {
    int i = blockIdx.x * blockDim.x + threadIdx.x;
    if (i >= n) return;
    float4 ag = g_aggx[i];
    float dv  = g_dinv[i];
    float a0 = ag.x * dv, a1 = ag.y * dv, a2 = ag.z * dv;
    g_av[i] = make_float4(a0, a1, a2, dv);
    uint2* dst = g_aggh + i * 8;
#pragma unroll
    for (int j = 0; j < 8; j++) {
        float f[4];
#pragma unroll
        for (int k = 0; k < 4; k++) {
            int c = 4 * j + k;
            float h = fmaf(a0, W0[c], fmaf(a1, W0[32 + c], fmaf(a2, W0[64 + c], b0[c])));
            f[k] = fmaxf(h, 0.f) * dv;
        }
        half2 lo = __floats2half2_rn(f[0], f[1]);
        half2 hi = __floats2half2_rn(f[2], f[3]);
        uint2 p;
        p.x = *(unsigned int*)&lo;
        p.y = *(unsigned int*)&hi;
        dst[j] = p;
    }
}

// K6: layer-1 edge pass, rank-3 recompute, fully-unrolled NE=4 strip with
// hoisted gathers (MLP=4). Quad of 4 lanes per edge; lane j owns features
// [8j,8j+8). Per edge: 1 broadcast av gather + 24 FMA + 1 red.v4.f16x2.
#define NE 4
__global__ void k_edge1(const int* __restrict__ idx, const float* __restrict__ w,
                        const float* __restrict__ W0, const float* __restrict__ b0, int E) {
    int t  = blockIdx.x * blockDim.x + threadIdx.x;
    int qd = t >> 2;          // quad id
    int j  = t & 3;           // lane-in-quad
    int e0 = qd * NE;
    if (e0 >= E) return;
    float w0r[8], w1r[8], w2r[8], b0r[8];
#pragma unroll
    for (int k = 0; k < 8; k++) {
        int c = 8 * j + k;
        w0r[k] = W0[c]; w1r[k] = W0[32 + c]; w2r[k] = W0[64 + c]; b0r[k] = b0[c];
    }
    if (e0 + NE <= E) {
        // full strip: hoist all loads, then compute+red
        int   rows[NE], cols[NE];
        float ws[NE];
        float4 avs[NE];
#pragma unroll
        for (int i = 0; i < NE; i++) {
            rows[i] = idx[e0 + i];
            cols[i] = idx[E + e0 + i];
            ws[i]   = w[e0 + i];
        }
#pragma unroll
        for (int i = 0; i < NE; i++) avs[i] = __ldg(g_av + rows[i]);
#pragma unroll
        for (int i = 0; i < NE; i++) {
            float4 av = avs[i];
            float s = av.w * ws[i];
            float f[8];
#pragma unroll
            for (int k = 0; k < 8; k++) {
                float h = fmaf(av.x, w0r[k], fmaf(av.y, w1r[k], fmaf(av.z, w2r[k], b0r[k])));
                f[k] = fmaxf(h, 0.f) * s;
            }
            half2 p0 = __floats2half2_rn(f[0], f[1]);
            half2 p1 = __floats2half2_rn(f[2], f[3]);
            half2 p2 = __floats2half2_rn(f[4], f[5]);
            half2 p3 = __floats2half2_rn(f[6], f[7]);
            red_add_v4h(&((uint4*)g_aggh)[cols[i] * 4 + j],
                        *(unsigned int*)&p0, *(unsigned int*)&p1,
                        *(unsigned int*)&p2, *(unsigned int*)&p3);
        }
    } else {
        for (int e = e0; e < E; e++) {
            int row = idx[e];
            int col = idx[E + e];
            float ww = w[e];
            float4 av = __ldg(g_av + row);
            float s = av.w * ww;
            float f[8];
#pragma unroll
            for (int k = 0; k < 8; k++) {
                float h = fmaf(av.x, w0r[k], fmaf(av.y, w1r[k], fmaf(av.z, w2r[k], b0r[k])));
                f[k] = fmaxf(h, 0.f) * s;
            }
            half2 p0 = __floats2half2_rn(f[0], f[1]);
            half2 p1 = __floats2half2_rn(f[2], f[3]);
            half2 p2 = __floats2half2_rn(f[4], f[5]);
            half2 p3 = __floats2half2_rn(f[6], f[7]);
            red_add_v4h(&((uint4*)g_aggh)[col * 4 + j],
                        *(unsigned int*)&p0, *(unsigned int*)&p1,
                        *(unsigned int*)&p2, *(unsigned int*)&p3);
        }
    }
}

// K7: per-graph block: h2 = relu(dinv*agg1 @ W1 + b1), mean-pool over
// sorted-batch range (binary search), head dot with Wr.
__global__ void k_pool(const int* __restrict__ batch,
                       const float* __restrict__ W1, const float* __restrict__ b1,
                       const float* __restrict__ Wr, const float* __restrict__ br,
                       float* __restrict__ out, int n) {
    int g = blockIdx.x;
    __shared__ float sW1[32 * 32];
    __shared__ float sb1[32];
    __shared__ float sWr[32];
    __shared__ int   sse[2];
    __shared__ float stile[8][33];
    __shared__ float spool[8][32];
    int tid = threadIdx.x;  // 256 threads
    for (int k = tid; k < 1024; k += 256) sW1[k] = W1[k];
    if (tid < 32) { sb1[tid] = b1[tid]; sWr[tid] = Wr[tid]; }
    if (tid < 2) {
        int key = g + tid;
        int lo = 0, hi = n;
        while (lo < hi) { int mid = (lo + hi) >> 1; if (batch[mid] < key) lo = mid + 1; else hi = mid; }
        sse[tid] = lo;
    }
    __syncthreads();
    int start = sse[0], end = sse[1];
    int feat = tid & 31, slot = tid >> 5;
    const __half* agg = (const __half*)g_aggh;
    float acc = 0.f;
    for (int base = start; base < end; base += 8) {
        int nload = min(8, end - base);
        __syncthreads();
        if (slot < nload) {
            int node = base + slot;
            stile[slot][feat] = g_dinv[node] * __half2float(agg[(size_t)node * 32 + feat]);
        }
        __syncthreads();
        if (slot < nload) {
            float v = sb1[feat];
#pragma unroll
            for (int jj = 0; jj < 32; jj++) v = fmaf(stile[slot][jj], sW1[jj * 32 + feat], v);
            acc += fmaxf(v, 0.f);
        }
    }
    spool[slot][feat] = acc;
    __syncthreads();
    if (tid < 32) {
        float s = 0.f;
#pragma unroll
        for (int k = 0; k < 8; k++) s += spool[k][tid];
        float cnt = (float)(end - start);
        float hg = s / fmaxf(cnt, 1.f);
        float p = hg * sWr[tid];
#pragma unroll
        for (int off = 16; off; off >>= 1) p += __shfl_down_sync(0xffffffffu, p, off);
        if (tid == 0) out[g] = p + br[0];
    }
}

extern "C" void kernel_launch(void* const* d_in, const int* in_sizes, int n_in,
                              void* d_out, int out_size) {
    const float* x     = (const float*)d_in[0];
    const int*   ei    = (const int*)d_in[1];
    const float* ew    = (const float*)d_in[2];
    const int*   batch = (const int*)d_in[3];
    const float* W0    = (const float*)d_in[4];
    const float* b0    = (const float*)d_in[5];
    const float* W1    = (const float*)d_in[6];
    const float* b1    = (const float*)d_in[7];
    const float* Wr    = (const float*)d_in[8];
    const float* br    = (const float*)d_in[9];
    float* out = (float*)d_out;

    int n = in_sizes[0] / 3;
    int E = in_sizes[2];
    int G = out_size;
    const int TB = 256;

    k_init <<<(n + TB - 1) / TB, TB>>>(n);
    k_deg  <<<(E + TB - 1) / TB, TB>>>(ei, ew, E);
    k_dinv <<<(n + TB - 1) / TB, TB>>>(x, n);
    k_edge0<<<(E + TB - 1) / TB, TB>>>(ei, ew, E);
    k_node0<<<(n + TB - 1) / TB, TB>>>(W0, b0, n);
    long long quads = ((long long)E + NE - 1) / NE;
    long long t1 = quads * 4;
    k_edge1<<<(int)((t1 + TB - 1) / TB), TB>>>(ei, ew, W0, b0, E);
    k_pool <<<G, 256>>>(batch, W1, b1, Wr, br, out, n);
}

// round 15
// speedup vs baseline: 1.9504x; 1.0326x over previous
#include <cuda_runtime.h>
#include <cuda_fp16.h>
#include <cstdint>

#define MAXN 100000

// ---- device scratch (no allocations allowed) ----
// g_deg starts zeroed (module load) and is reset to 0 by k_dinv each run:
// self-cleaning across graph replays, so no init kernel is needed.
__device__ float g_deg [MAXN];
__device__ float g_dinv[MAXN];
__device__ __align__(128) float4 g_xp  [MAXN];      // xs = dinv*x, padded (w=0)
__device__ __align__(128) float4 g_aggx[MAXN];      // layer-0 agg of xs (fp32)
__device__ __align__(128) float4 g_av  [MAXN];      // (a0,a1,a2,dinv): rank-3 h1 code
__device__ __align__(128) uint2  g_aggh[MAXN * 8];  // layer-1 agg fp16 [N x 32]

__device__ __forceinline__ void red_add_v4f(float4* addr, float4 v) {
    atomicAdd(addr, v);   // native fp32 vector red (cc >= 9.0)
}
__device__ __forceinline__ void red_add_v4h(void* addr, unsigned int a, unsigned int b,
                                            unsigned int c, unsigned int d) {
    asm volatile("red.global.add.noftz.v4.f16x2 [%0], {%1,%2,%3,%4};"
                 :: "l"(__cvta_generic_to_global(addr)),
                    "r"(a), "r"(b), "r"(c), "r"(d) : "memory");
}

// K2: deg[col] += w, 2 edges per thread (vectorized idx/w loads, E even-fast-path)
__global__ void k_deg(const int* __restrict__ idx, const float* __restrict__ w, int E) {
    int t = blockIdx.x * blockDim.x + threadIdx.x;
    int e = t * 2;
    if (e + 1 < E) {
        int2   c2 = *(const int2*)(idx + E + e);
        float2 w2 = *(const float2*)(w + e);
        atomicAdd(&g_deg[c2.x], w2.x);
        atomicAdd(&g_deg[c2.y], w2.y);
    } else if (e < E) {
        atomicAdd(&g_deg[idx[E + e]], w[e]);
    }
}

// K3: dinv = rsqrt(1+deg) (self-loop folded); reset deg to 0 for next replay;
// xs = dinv*x; seed layer-0 agg with self term xs.
__global__ void k_dinv(const float* __restrict__ x, int n) {
    int i = blockIdx.x * blockDim.x + threadIdx.x;
    if (i >= n) return;
    float d = g_deg[i];
    g_deg[i] = 0.f;                       // self-clean for graph replay
    float dv = rsqrtf(1.0f + d);
    g_dinv[i] = dv;
    float4 xs = make_float4(x[3*i] * dv, x[3*i+1] * dv, x[3*i+2] * dv, 0.f);
    g_xp[i]   = xs;
    g_aggx[i] = xs;
}

// K4: layer-0 edge pass (factorized norm), fp32 red.v4
__global__ void k_edge0(const int* __restrict__ idx, const float* __restrict__ w, int E) {
    int e = blockIdx.x * blockDim.x + threadIdx.x;
    if (e >= E) return;
    int row = idx[e];
    int col = idx[E + e];
    float ww = w[e];
    float4 v = g_xp[row];
    red_add_v4f(&g_aggx[col], make_float4(v.x * ww, v.y * ww, v.z * ww, 0.f));
}

// K5: per node: a = dinv*agg0; store (a,dinv); seed layer-1 agg with self
// h1 = dinv*relu(a@W0 + b0) in fp16. Thread per node (light compute).
__global__ void k_node0(const float* __restrict__ W0, const float* __restrict__ b0, int n) {
    int i = blockIdx.x * blockDim.x + threadIdx.x;
    if (i >= n) return;
    float4 ag = g_aggx[i];
    float dv  = g_dinv[i];
    float a0 = ag.x * dv, a1 = ag.y * dv, a2 = ag.z * dv;
    g_av[i] = make_float4(a0, a1, a2, dv);
    uint2* dst = g_aggh + i * 8;
#pragma unroll
    for (int j = 0; j < 8; j++) {
        float f[4];
#pragma unroll
        for (int k = 0; k < 4; k++) {
            int c = 4 * j + k;
            float h = fmaf(a0, W0[c], fmaf(a1, W0[32 + c], fmaf(a2, W0[64 + c], b0[c])));
            f[k] = fmaxf(h, 0.f) * dv;
        }
        half2 lo = __floats2half2_rn(f[0], f[1]);
        half2 hi = __floats2half2_rn(f[2], f[3]);
        uint2 p;
        p.x = *(unsigned int*)&lo;
        p.y = *(unsigned int*)&hi;
        dst[j] = p;
    }
}

// K6: layer-1 edge pass, rank-3 recompute (R11 best variant). Quad of 4 lanes
// owns a strip of NE edges; lane j owns features [8j,8j+8). Per edge: one 16B
// broadcast av gather, 24 FMA recompute, one red.v4.f16x2 (16B).
#define NE 8
__global__ void k_edge1(const int* __restrict__ idx, const float* __restrict__ w,
                        const float* __restrict__ W0, const float* __restrict__ b0, int E) {
    int t  = blockIdx.x * blockDim.x + threadIdx.x;
    int qd = t >> 2;          // quad id
    int j  = t & 3;           // lane-in-quad
    int e0 = qd * NE;
    if (e0 >= E) return;
    float w0r[8], w1r[8], w2r[8], b0r[8];
#pragma unroll
    for (int k = 0; k < 8; k++) {
        int c = 8 * j + k;
        w0r[k] = W0[c]; w1r[k] = W0[32 + c]; w2r[k] = W0[64 + c]; b0r[k] = b0[c];
    }
    int eend = min(e0 + NE, E);
    for (int e = e0; e < eend; e++) {
        int row = idx[e];
        int col = idx[E + e];
        float ww = w[e];
        float4 av = __ldg(g_av + row);          // 16B, quad-broadcast (1 sector)
        float s = av.w * ww;                    // dinv_row * w_e
        float f[8];
#pragma unroll
        for (int k = 0; k < 8; k++) {
            float h = fmaf(av.x, w0r[k], fmaf(av.y, w1r[k], fmaf(av.z, w2r[k], b0r[k])));
            f[k] = fmaxf(h, 0.f) * s;
        }
        half2 p0 = __floats2half2_rn(f[0], f[1]);
        half2 p1 = __floats2half2_rn(f[2], f[3]);
        half2 p2 = __floats2half2_rn(f[4], f[5]);
        half2 p3 = __floats2half2_rn(f[6], f[7]);
        red_add_v4h(&((uint4*)g_aggh)[col * 4 + j],
                    *(unsigned int*)&p0, *(unsigned int*)&p1,
                    *(unsigned int*)&p2, *(unsigned int*)&p3);
    }
}

// K7: per-graph block: h2 = relu(dinv*agg1 @ W1 + b1), mean-pool over
// sorted-batch range (binary search), head dot with Wr.
__global__ void k_pool(const int* __restrict__ batch,
                       const float* __restrict__ W1, const float* __restrict__ b1,
                       const float* __restrict__ Wr, const float* __restrict__ br,
                       float* __restrict__ out, int n) {
    int g = blockIdx.x;
    __shared__ float sW1[32 * 32];
    __shared__ float sb1[32];
    __shared__ float sWr[32];
    __shared__ int   sse[2];
    __shared__ float stile[8][33];
    __shared__ float spool[8][32];
    int tid = threadIdx.x;  // 256 threads
    for (int k = tid; k < 1024; k += 256) sW1[k] = W1[k];
    if (tid < 32) { sb1[tid] = b1[tid]; sWr[tid] = Wr[tid]; }
    if (tid < 2) {
        int key = g + tid;
        int lo = 0, hi = n;
        while (lo < hi) { int mid = (lo + hi) >> 1; if (batch[mid] < key) lo = mid + 1; else hi = mid; }
        sse[tid] = lo;
    }
    __syncthreads();
    int start = sse[0], end = sse[1];
    int feat = tid & 31, slot = tid >> 5;
    const __half* agg = (const __half*)g_aggh;
    float acc = 0.f;
    for (int base = start; base < end; base += 8) {
        int nload = min(8, end - base);
        __syncthreads();
        if (slot < nload) {
            int node = base + slot;
            stile[slot][feat] = g_dinv[node] * __half2float(agg[(size_t)node * 32 + feat]);
        }
        __syncthreads();
        if (slot < nload) {
            float v = sb1[feat];
#pragma unroll
            for (int jj = 0; jj < 32; jj++) v = fmaf(stile[slot][jj], sW1[jj * 32 + feat], v);
            acc += fmaxf(v, 0.f);
        }
    }
    spool[slot][feat] = acc;
    __syncthreads();
    if (tid < 32) {
        float s = 0.f;
#pragma unroll
        for (int k = 0; k < 8; k++) s += spool[k][tid];
        float cnt = (float)(end - start);
        float hg = s / fmaxf(cnt, 1.f);
        float p = hg * sWr[tid];
#pragma unroll
        for (int off = 16; off; off >>= 1) p += __shfl_down_sync(0xffffffffu, p, off);
        if (tid == 0) out[g] = p + br[0];
    }
}

extern "C" void kernel_launch(void* const* d_in, const int* in_sizes, int n_in,
                              void* d_out, int out_size) {
    const float* x     = (const float*)d_in[0];
    const int*   ei    = (const int*)d_in[1];
    const float* ew    = (const float*)d_in[2];
    const int*   batch = (const int*)d_in[3];
    const float* W0    = (const float*)d_in[4];
    const float* b0    = (const float*)d_in[5];
    const float* W1    = (const float*)d_in[6];
    const float* b1    = (const float*)d_in[7];
    const float* Wr    = (const float*)d_in[8];
    const float* br    = (const float*)d_in[9];
    float* out = (float*)d_out;

    int n = in_sizes[0] / 3;
    int E = in_sizes[2];
    int G = out_size;
    const int TB = 256;

    int degThreads = (E + 1) / 2;
    k_deg  <<<(degThreads + TB - 1) / TB, TB>>>(ei, ew, E);
    k_dinv <<<(n + TB - 1) / TB, TB>>>(x, n);
    k_edge0<<<(E + TB - 1) / TB, TB>>>(ei, ew, E);
    k_node0<<<(n + TB - 1) / TB, TB>>>(W0, b0, n);
    long long quads = ((long long)E + NE - 1) / NE;
    long long t1 = quads * 4;
    k_edge1<<<(int)((t1 + TB - 1) / TB), TB>>>(ei, ew, W0, b0, E);
    k_pool <<<G, 256>>>(batch, W1, b1, Wr, br, out, n);
}

// round 16
// speedup vs baseline: 1.9537x; 1.0017x over previous
#include <cuda_runtime.h>
#include <cuda_fp16.h>
#include <cstdint>

#define MAXN 100000

// ---- device scratch (no allocations allowed) ----
// g_deg starts zeroed (module load) and is reset to 0 by k_dinv each run:
// self-cleaning across graph replays, so no init kernel is needed.
__device__ float g_deg [MAXN];
__device__ float g_dinv[MAXN];
__device__ __align__(128) float4 g_xp  [MAXN];      // xs = dinv*x, padded (w=0)
__device__ __align__(128) float4 g_aggx[MAXN];      // layer-0 agg of xs (fp32)
__device__ __align__(128) float4 g_av  [MAXN];      // (a0,a1,a2,dinv): rank-3 h1 code
__device__ __align__(128) uint2  g_aggh[MAXN * 8];  // layer-1 agg fp16 [N x 32]

__device__ __forceinline__ void red_add_v4f(float4* addr, float4 v) {
    atomicAdd(addr, v);   // native fp32 vector red (cc >= 9.0)
}
__device__ __forceinline__ void red_add_v4h(void* addr, unsigned int a, unsigned int b,
                                            unsigned int c, unsigned int d) {
    asm volatile("red.global.add.noftz.v4.f16x2 [%0], {%1,%2,%3,%4};"
                 :: "l"(__cvta_generic_to_global(addr)),
                    "r"(a), "r"(b), "r"(c), "r"(d) : "memory");
}

// K2: deg[col] += w, 2 edges per thread (vectorized idx/w loads)
__global__ void k_deg(const int* __restrict__ idx, const float* __restrict__ w, int E) {
    int t = blockIdx.x * blockDim.x + threadIdx.x;
    int e = t * 2;
    if (e + 1 < E) {
        int2   c2 = *(const int2*)(idx + E + e);
        float2 w2 = *(const float2*)(w + e);
        atomicAdd(&g_deg[c2.x], w2.x);
        atomicAdd(&g_deg[c2.y], w2.y);
    } else if (e < E) {
        atomicAdd(&g_deg[idx[E + e]], w[e]);
    }
}

// K3: dinv = rsqrt(1+deg) (self-loop folded); reset deg to 0 for next replay;
// xs = dinv*x; seed layer-0 agg with self term xs.
__global__ void k_dinv(const float* __restrict__ x, int n) {
    int i = blockIdx.x * blockDim.x + threadIdx.x;
    if (i >= n) return;
    float d = g_deg[i];
    g_deg[i] = 0.f;                       // self-clean for graph replay
    float dv = rsqrtf(1.0f + d);
    g_dinv[i] = dv;
    float4 xs = make_float4(x[3*i] * dv, x[3*i+1] * dv, x[3*i+2] * dv, 0.f);
    g_xp[i]   = xs;
    g_aggx[i] = xs;
}

// K4: layer-0 edge pass (factorized norm), fp32 red.v4
__global__ void k_edge0(const int* __restrict__ idx, const float* __restrict__ w, int E) {
    int e = blockIdx.x * blockDim.x + threadIdx.x;
    if (e >= E) return;
    int row = idx[e];
    int col = idx[E + e];
    float ww = w[e];
    float4 v = g_xp[row];
    red_add_v4f(&g_aggx[col], make_float4(v.x * ww, v.y * ww, v.z * ww, 0.f));
}

// K5: 8 threads per node: a = dinv*agg0; lane 0 stores (a,dinv); each thread
// computes 4 features of the fp16 self-loop seed h1 = dinv*relu(a@W0+b0).
__global__ void k_node0(const float* __restrict__ W0, const float* __restrict__ b0, int n) {
    int t = blockIdx.x * blockDim.x + threadIdx.x;
    if (t >= n * 8) return;
    int i = t >> 3, j = t & 7;
    float4 ag = g_aggx[i];               // broadcast across the 8-thread group
    float dv  = g_dinv[i];
    float a0 = ag.x * dv, a1 = ag.y * dv, a2 = ag.z * dv;
    if (j == 0) g_av[i] = make_float4(a0, a1, a2, dv);
    float f[4];
#pragma unroll
    for (int k = 0; k < 4; k++) {
        int c = 4 * j + k;
        float h = fmaf(a0, W0[c], fmaf(a1, W0[32 + c], fmaf(a2, W0[64 + c], b0[c])));
        f[k] = fmaxf(h, 0.f) * dv;
    }
    half2 lo = __floats2half2_rn(f[0], f[1]);
    half2 hi = __floats2half2_rn(f[2], f[3]);
    uint2 p;
    p.x = *(unsigned int*)&lo;
    p.y = *(unsigned int*)&hi;
    g_aggh[t] = p;
}

// K6: layer-1 edge pass, rank-3 recompute (R11 best variant). Quad of 4 lanes
// owns a strip of NE edges; lane j owns features [8j,8j+8). Per edge: one 16B
// broadcast av gather, 24 FMA recompute, one red.v4.f16x2 (16B).
#define NE 8
__global__ void k_edge1(const int* __restrict__ idx, const float* __restrict__ w,
                        const float* __restrict__ W0, const float* __restrict__ b0, int E) {
    int t  = blockIdx.x * blockDim.x + threadIdx.x;
    int qd = t >> 2;          // quad id
    int j  = t & 3;           // lane-in-quad
    int e0 = qd * NE;
    if (e0 >= E) return;
    float w0r[8], w1r[8], w2r[8], b0r[8];
#pragma unroll
    for (int k = 0; k < 8; k++) {
        int c = 8 * j + k;
        w0r[k] = W0[c]; w1r[k] = W0[32 + c]; w2r[k] = W0[64 + c]; b0r[k] = b0[c];
    }
    int eend = min(e0 + NE, E);
    for (int e = e0; e < eend; e++) {
        int row = idx[e];
        int col = idx[E + e];
        float ww = w[e];
        float4 av = __ldg(g_av + row);          // 16B, quad-broadcast (1 sector)
        float s = av.w * ww;                    // dinv_row * w_e
        float f[8];
#pragma unroll
        for (int k = 0; k < 8; k++) {
            float h = fmaf(av.x, w0r[k], fmaf(av.y, w1r[k], fmaf(av.z, w2r[k], b0r[k])));
            f[k] = fmaxf(h, 0.f) * s;
        }
        half2 p0 = __floats2half2_rn(f[0], f[1]);
        half2 p1 = __floats2half2_rn(f[2], f[3]);
        half2 p2 = __floats2half2_rn(f[4], f[5]);
        half2 p3 = __floats2half2_rn(f[6], f[7]);
        red_add_v4h(&((uint4*)g_aggh)[col * 4 + j],
                    *(unsigned int*)&p0, *(unsigned int*)&p1,
                    *(unsigned int*)&p2, *(unsigned int*)&p3);
    }
}

// K7: per-graph block: h2 = relu(dinv*agg1 @ W1 + b1), mean-pool over
// sorted-batch range (binary search), head dot with Wr.
__global__ void k_pool(const int* __restrict__ batch,
                       const float* __restrict__ W1, const float* __restrict__ b1,
                       const float* __restrict__ Wr, const float* __restrict__ br,
                       float* __restrict__ out, int n) {
    int g = blockIdx.x;
    __shared__ float sW1[32 * 32];
    __shared__ float sb1[32];
    __shared__ float sWr[32];
    __shared__ int   sse[2];
    __shared__ float stile[8][33];
    __shared__ float spool[8][32];
    int tid = threadIdx.x;  // 256 threads
    for (int k = tid; k < 1024; k += 256) sW1[k] = W1[k];
    if (tid < 32) { sb1[tid] = b1[tid]; sWr[tid] = Wr[tid]; }
    if (tid < 2) {
        int key = g + tid;
        int lo = 0, hi = n;
        while (lo < hi) { int mid = (lo + hi) >> 1; if (batch[mid] < key) lo = mid + 1; else hi = mid; }
        sse[tid] = lo;
    }
    __syncthreads();
    int start = sse[0], end = sse[1];
    int feat = tid & 31, slot = tid >> 5;
    const __half* agg = (const __half*)g_aggh;
    float acc = 0.f;
    for (int base = start; base < end; base += 8) {
        int nload = min(8, end - base);
        __syncthreads();
        if (slot < nload) {
            int node = base + slot;
            stile[slot][feat] = g_dinv[node] * __half2float(agg[(size_t)node * 32 + feat]);
        }
        __syncthreads();
        if (slot < nload) {
            float v = sb1[feat];
#pragma unroll
            for (int jj = 0; jj < 32; jj++) v = fmaf(stile[slot][jj], sW1[jj * 32 + feat], v);
            acc += fmaxf(v, 0.f);
        }
    }
    spool[slot][feat] = acc;
    __syncthreads();
    if (tid < 32) {
        float s = 0.f;
#pragma unroll
        for (int k = 0; k < 8; k++) s += spool[k][tid];
        float cnt = (float)(end - start);
        float hg = s / fmaxf(cnt, 1.f);
        float p = hg * sWr[tid];
#pragma unroll
        for (int off = 16; off; off >>= 1) p += __shfl_down_sync(0xffffffffu, p, off);
        if (tid == 0) out[g] = p + br[0];
    }
}

extern "C" void kernel_launch(void* const* d_in, const int* in_sizes, int n_in,
                              void* d_out, int out_size) {
    const float* x     = (const float*)d_in[0];
    const int*   ei    = (const int*)d_in[1];
    const float* ew    = (const float*)d_in[2];
    const int*   batch = (const int*)d_in[3];
    const float* W0    = (const float*)d_in[4];
    const float* b0    = (const float*)d_in[5];
    const float* W1    = (const float*)d_in[6];
    const float* b1    = (const float*)d_in[7];
    const float* Wr    = (const float*)d_in[8];
    const float* br    = (const float*)d_in[9];
    float* out = (float*)d_out;

    int n = in_sizes[0] / 3;
    int E = in_sizes[2];
    int G = out_size;
    const int TB = 256;

    int degThreads = (E + 1) / 2;
    k_deg  <<<(degThreads + TB - 1) / TB, TB>>>(ei, ew, E);
    k_dinv <<<(n + TB - 1) / TB, TB>>>(x, n);
    k_edge0<<<(E + TB - 1) / TB, TB>>>(ei, ew, E);
    k_node0<<<(n * 8 + TB - 1) / TB, TB>>>(W0, b0, n);
    long long quads = ((long long)E + NE - 1) / NE;
    long long t1 = quads * 4;
    k_edge1<<<(int)((t1 + TB - 1) / TB), TB>>>(ei, ew, W0, b0, E);
    k_pool <<<G, 256>>>(batch, W1, b1, Wr, br, out, n);
}